// round 10
// baseline (speedup 1.0000x reference)
#include <cuda_runtime.h>
#include <cstdint>

// B=8, C=16, H=512, W=512, M=N=15
//   K:     [128, 16, 16]  f32
//   basis: [262144, 16, 16] f32, separable: basis[h*W+w,p,q] = Bu[h,p]*Bv[w,q]
//   out:   [128, 512, 512] f32
//
// Bu[h,p] = sum_q basis[h*W, p, q]; Bv[w,q] = sum_p basis[w, p, q]
// T[bc,p,w] = sum_q K[bc,p,q]*Bv[w,q];  out[bc,h,w] = sum_p Bu[h,p]*T[bc,p,w]

#define HH 512
#define WW 512
#define PP 16
#define QQ 16
#define BC 128
#define ROWS 128

__device__ float g_But[PP * HH];   // Bu transposed: [p][h], 32 KB
__device__ float g_BvT[QQ * WW];   // Bv transposed: [q][w], 32 KB

__device__ __forceinline__ unsigned long long pk(float a, float b) {
    unsigned long long r;
    asm("mov.b64 %0, {%1, %2};" : "=l"(r) : "f"(a), "f"(b));
    return r;
}
__device__ __forceinline__ void fma2(unsigned long long& d, unsigned long long a,
                                     unsigned long long b) {
    asm("fma.rn.f32x2 %0, %1, %2, %0;" : "+l"(d) : "l"(a), "l"(b));
}
__device__ __forceinline__ void unpk(unsigned long long v, float& a, float& b) {
    asm("mov.b64 {%0, %1}, %2;" : "=f"(a), "=f"(b) : "l"(v));
}

// ---------------------------------------------------------------------------
// Kernel A: extraction. Warp-per-row, coalesced loads, shfl reductions.
//   blocks 0..63  : Bu rows (h = 8*blk + warp)
//   blocks 64..127: Bv rows (w = 8*(blk-64) + warp)
// ---------------------------------------------------------------------------
__global__ __launch_bounds__(256) void extract_factors(const float* __restrict__ basis) {
    int warp = threadIdx.x >> 5, lane = threadIdx.x & 31;
    if (blockIdx.x < 64) {
        int h = blockIdx.x * 8 + warp;
        const float4* r4 = reinterpret_cast<const float4*>(basis + (size_t)h * WW * (PP * QQ));
        float4 a = r4[lane * 2];
        float4 b = r4[lane * 2 + 1];
        float s = (a.x + a.y) + (a.z + a.w) + (b.x + b.y) + (b.z + b.w);
        s += __shfl_xor_sync(0xffffffffu, s, 1);   // lanes (2k,2k+1) cover p=k
        if ((lane & 1) == 0) g_But[(lane >> 1) * HH + h] = s;
    } else {
        int w = (blockIdx.x - 64) * 8 + warp;
        const float4* r4 = reinterpret_cast<const float4*>(basis + (size_t)w * (PP * QQ));
        float4 a = r4[lane * 2];
        float4 b = r4[lane * 2 + 1];
        // lane l: p = l>>1, q = (l&1)*8 + j; butterfly over p (offsets 2..16)
        #pragma unroll
        for (int off = 2; off <= 16; off <<= 1) {
            a.x += __shfl_xor_sync(0xffffffffu, a.x, off);
            a.y += __shfl_xor_sync(0xffffffffu, a.y, off);
            a.z += __shfl_xor_sync(0xffffffffu, a.z, off);
            a.w += __shfl_xor_sync(0xffffffffu, a.w, off);
            b.x += __shfl_xor_sync(0xffffffffu, b.x, off);
            b.y += __shfl_xor_sync(0xffffffffu, b.y, off);
            b.z += __shfl_xor_sync(0xffffffffu, b.z, off);
            b.w += __shfl_xor_sync(0xffffffffu, b.w, off);
        }
        if (lane < 2) {
            int q0 = lane * 8;
            g_BvT[(q0 + 0) * WW + w] = a.x;
            g_BvT[(q0 + 1) * WW + w] = a.y;
            g_BvT[(q0 + 2) * WW + w] = a.z;
            g_BvT[(q0 + 3) * WW + w] = a.w;
            g_BvT[(q0 + 4) * WW + w] = b.x;
            g_BvT[(q0 + 5) * WW + w] = b.y;
            g_BvT[(q0 + 6) * WW + w] = b.z;
            g_BvT[(q0 + 7) * WW + w] = b.w;
        }
    }
}

// ---------------------------------------------------------------------------
// Kernel B (fused, h-packed, 2 w/thread — no spills):
//   grid (H/ROWS=4, BC), 256 threads; thread t owns w = 2t, 2t+1.
//   Prologue: T natural w-pairs streamed over q (dup'd K in smem, LDS.64
//             broadcast), then dup'd once into Td0/Td1 (32 u64 = 64 regs).
//   Main: per 4-row group, per p: 1 broadcast LDS.128 of natural Bu pairs
//         + 4 FFMA2 on 4 independent chains.
// ---------------------------------------------------------------------------
__global__ __launch_bounds__(256) void fused_stage(const float* __restrict__ K,
                                                   float* __restrict__ out) {
    int bc = blockIdx.y;
    int h0 = blockIdx.x * ROWS;
    int t = threadIdx.x;

    __shared__ unsigned long long sK2[PP * QQ];  // dup'd (k,k), 2 KB
    __shared__ float sBu[PP * ROWS];             // [p][hh], 8 KB

    // Stage K[bc] duplicated (one float per thread)
    {
        float k = K[(size_t)bc * (PP * QQ) + t];
        sK2[t] = pk(k, k);
    }
    // Stage Bu tile (coalesced float4 copy: 512 float4, 2 iters)
    {
        const float4* src = reinterpret_cast<const float4*>(g_But);
        float4* dst = reinterpret_cast<float4*>(sBu);
        #pragma unroll
        for (int i = t; i < PP * ROWS / 4; i += 256) {
            int p = i >> 5, c = i & 31;
            dst[i] = src[(p * HH + h0) / 4 + c];
        }
    }
    __syncthreads();

    // Prologue: T[p] as natural w-pair, streaming q from g_BvT (coalesced)
    unsigned long long Tp[PP];
    #pragma unroll
    for (int p = 0; p < PP; ++p) Tp[p] = 0ull;
    {
        const float2* bvt2 = reinterpret_cast<const float2*>(g_BvT);
        #pragma unroll
        for (int q = 0; q < QQ; ++q) {
            float2 v = bvt2[q * (WW / 2) + t];        // LDG.64 coalesced
            unsigned long long vp = pk(v.x, v.y);
            #pragma unroll
            for (int p = 0; p < PP; ++p)
                fma2(Tp[p], sK2[p * QQ + q], vp);     // LDS.64 broadcast
        }
    }
    // Duplicate into per-w pairs (Tp dies here; no spill)
    unsigned long long Td0[PP], Td1[PP];
    #pragma unroll
    for (int p = 0; p < PP; ++p) {
        float t0, t1;
        unpk(Tp[p], t0, t1);
        Td0[p] = pk(t0, t0);
        Td1[p] = pk(t1, t1);
    }

    float* obase = out + (size_t)bc * HH * WW + (size_t)h0 * WW + 2 * t;

    #pragma unroll 2
    for (int g = 0; g < ROWS; g += 4) {
        unsigned long long a0 = 0ull, a1 = 0ull;  // rows (g, g+1), w0 / w1
        unsigned long long b0 = 0ull, b1 = 0ull;  // rows (g+2, g+3), w0 / w1

        #pragma unroll
        for (int p = 0; p < PP; ++p) {
            // natural Bu pairs: (bu_g, bu_g+1), (bu_g+2, bu_g+3); broadcast LDS.128
            ulonglong2 v = *reinterpret_cast<const ulonglong2*>(&sBu[p * ROWS + g]);
            fma2(a0, v.x, Td0[p]);
            fma2(a1, v.x, Td1[p]);
            fma2(b0, v.y, Td0[p]);
            fma2(b1, v.y, Td1[p]);
        }

        float r0w0, r1w0, r0w1, r1w1, r2w0, r3w0, r2w1, r3w1;
        unpk(a0, r0w0, r1w0);
        unpk(a1, r0w1, r1w1);
        unpk(b0, r2w0, r3w0);
        unpk(b1, r2w1, r3w1);
        *reinterpret_cast<float2*>(obase + (size_t)(g + 0) * WW) = make_float2(r0w0, r0w1);
        *reinterpret_cast<float2*>(obase + (size_t)(g + 1) * WW) = make_float2(r1w0, r1w1);
        *reinterpret_cast<float2*>(obase + (size_t)(g + 2) * WW) = make_float2(r2w0, r2w1);
        *reinterpret_cast<float2*>(obase + (size_t)(g + 3) * WW) = make_float2(r3w0, r3w1);
    }
}

// ---------------------------------------------------------------------------
extern "C" void kernel_launch(void* const* d_in, const int* in_sizes, int n_in,
                              void* d_out, int out_size) {
    const float* K     = (const float*)d_in[0];
    const float* basis = (const float*)d_in[1];
    float* out = (float*)d_out;
    (void)in_sizes; (void)n_in; (void)out_size;

    extract_factors<<<128, 256>>>(basis);

    dim3 g2(HH / ROWS, BC);
    fused_stage<<<g2, 256>>>(K, out);
}